// round 1
// baseline (speedup 1.0000x reference)
#include <cuda_runtime.h>
#include <cuda_bf16.h>

#define NNODES 100000
#define CAP 2048

// Scratch (device globals — no allocation allowed)
__device__ int           g_deg[NNODES];
__device__ float         g_dinv[NNODES];
__device__ float         g_s[NNODES];
__device__ unsigned char g_needed[NNODES];
__device__ int           g_last_src[CAP];
__device__ int           g_count;
__device__ int           g_mode64;

// ---------------------------------------------------------------------------
// Detect whether edge_index is int64 or int32. For int64 (values < 2^31,
// little-endian) every odd 32-bit word is 0; for int32 random indices in
// [0,100000) the chance of 32 consecutive zeros is ~1e-160.
__global__ void detect_kernel(const unsigned int* __restrict__ idx) {
    if (threadIdx.x == 0) {
        int all0 = 1;
        #pragma unroll
        for (int i = 0; i < 32; i++)
            if (idx[2 * i + 1] != 0u) all0 = 0;
        g_mode64 = all0;
    }
}

// ---------------------------------------------------------------------------
__global__ void zero_kernel() {
    int i = blockIdx.x * blockDim.x + threadIdx.x;
    int stride = gridDim.x * blockDim.x;
    for (int n = i; n < NNODES; n += stride) {
        g_deg[n] = 0;
        g_s[n] = 0.0f;
        g_needed[n] = 0;
    }
    if (i == 0) g_count = 0;
}

// ---------------------------------------------------------------------------
// Pass A: in-degree of every node (dst half of edge_index) + collect src of
// all edges whose dst is the last node.
__global__ void degree_kernel(const void* __restrict__ eidx, int E) {
    const int mode = g_mode64;
    int i = blockIdx.x * blockDim.x + threadIdx.x;
    int stride = gridDim.x * blockDim.x;
    if (mode) {
        const long long* __restrict__ srcp = (const long long*)eidx;
        const long long* __restrict__ dstp = srcp + E;
        for (int e = i; e < E; e += stride) {
            int d = (int)dstp[e];
            atomicAdd(&g_deg[d], 1);
            if (d == NNODES - 1) {
                int pos = atomicAdd(&g_count, 1);
                if (pos < CAP) g_last_src[pos] = (int)srcp[e];
            }
        }
    } else {
        const int* __restrict__ srcp = (const int*)eidx;
        const int* __restrict__ dstp = srcp + E;
        for (int e = i; e < E; e += stride) {
            int d = dstp[e];
            atomicAdd(&g_deg[d], 1);
            if (d == NNODES - 1) {
                int pos = atomicAdd(&g_count, 1);
                if (pos < CAP) g_last_src[pos] = srcp[e];
            }
        }
    }
}

// ---------------------------------------------------------------------------
// dinv = rsqrt(deg + 1)  (self-loop included), and mark needed nodes.
__global__ void dinv_kernel() {
    int i = blockIdx.x * blockDim.x + threadIdx.x;
    int stride = gridDim.x * blockDim.x;
    for (int n = i; n < NNODES; n += stride)
        g_dinv[n] = rsqrtf((float)(g_deg[n] + 1));
    if (blockIdx.x == 0) {
        int c = g_count;
        if (c > CAP) c = CAP;
        for (int k = threadIdx.x; k < c; k += blockDim.x)
            g_needed[g_last_src[k]] = 1;
        if (threadIdx.x == 0) g_needed[NNODES - 1] = 1;
    }
}

// ---------------------------------------------------------------------------
// Pass B: layer-1 scalar aggregation, but ONLY for edges whose dst is needed.
__global__ void gather_kernel(const void* __restrict__ eidx,
                              const float* __restrict__ x, int E) {
    const int mode = g_mode64;
    int i = blockIdx.x * blockDim.x + threadIdx.x;
    int stride = gridDim.x * blockDim.x;
    if (mode) {
        const long long* __restrict__ srcp = (const long long*)eidx;
        const long long* __restrict__ dstp = srcp + E;
        for (int e = i; e < E; e += stride) {
            int d = (int)dstp[e];
            if (g_needed[d]) {
                int s = (int)srcp[e];
                atomicAdd(&g_s[d], x[s] * g_dinv[s] * g_dinv[d]);
            }
        }
    } else {
        const int* __restrict__ srcp = (const int*)eidx;
        const int* __restrict__ dstp = srcp + E;
        for (int e = i; e < E; e += stride) {
            int d = dstp[e];
            if (g_needed[d]) {
                int s = srcp[e];
                atomicAdd(&g_s[d], x[s] * g_dinv[s] * g_dinv[d]);
            }
        }
    }
}

// ---------------------------------------------------------------------------
// Final: layer-2 aggregation at node N-1 only, then fc head. One warp.
__global__ void final_kernel(const float* __restrict__ x,
                             const float* __restrict__ W1,
                             const float* __restrict__ b1,
                             const float* __restrict__ W2,
                             const float* __restrict__ b2,
                             const float* __restrict__ Wfc,
                             const float* __restrict__ bfc,
                             float* __restrict__ out) {
    int lane = threadIdx.x;  // blockDim.x == 32
    __shared__ float sW1[16], sb1[16], sW2[128], sb2[8], sWfc[8];
    if (lane < 16) { sW1[lane] = W1[lane]; sb1[lane] = b1[lane]; }
    if (lane < 8)  { sb2[lane] = b2[lane]; sWfc[lane] = Wfc[lane]; }
    for (int k = lane; k < 128; k += 32) sW2[k] = W2[k];
    __syncwarp();

    const float dinvL = g_dinv[NNODES - 1];
    int c = g_count;
    if (c > CAP) c = CAP;

    float agg[8];
    #pragma unroll
    for (int j = 0; j < 8; j++) agg[j] = 0.0f;

    // k in [0, c): real edges into N-1; k == c: the appended self-loop.
    for (int k = lane; k <= c; k += 32) {
        int u = (k == c) ? (NNODES - 1) : g_last_src[k];
        float du = g_dinv[u];
        float norm = du * dinvL;
        // layer-1 value at u: aggregated edges (g_s) + layer-1 self-loop term
        float su = g_s[u] + x[u] * du * du;
        float h1[16];
        #pragma unroll
        for (int j = 0; j < 16; j++)
            h1[j] = fmaxf(fmaf(su, sW1[j], sb1[j]), 0.0f);
        #pragma unroll
        for (int j = 0; j < 8; j++) {
            float v = 0.0f;
            #pragma unroll
            for (int t = 0; t < 16; t++) v = fmaf(h1[t], sW2[t * 8 + j], v);
            agg[j] = fmaf(v, norm, agg[j]);
        }
    }

    // warp reduction
    #pragma unroll
    for (int off = 16; off > 0; off >>= 1) {
        #pragma unroll
        for (int j = 0; j < 8; j++)
            agg[j] += __shfl_down_sync(0xffffffff, agg[j], off);
    }

    if (lane == 0) {
        float o = bfc[0];
        #pragma unroll
        for (int j = 0; j < 8; j++) {
            float h2 = fmaxf(agg[j] + sb2[j], 0.0f);
            o = fmaf(h2, sWfc[j], o);
        }
        out[0] = o;
    }
}

// ---------------------------------------------------------------------------
extern "C" void kernel_launch(void* const* d_in, const int* in_sizes, int n_in,
                              void* d_out, int out_size) {
    const float* x    = (const float*)d_in[0];
    const void*  eidx = d_in[1];
    const float* W1   = (const float*)d_in[2];
    const float* b1   = (const float*)d_in[3];
    const float* W2   = (const float*)d_in[4];
    const float* b2   = (const float*)d_in[5];
    const float* Wfc  = (const float*)d_in[6];
    const float* bfc  = (const float*)d_in[7];
    float* out = (float*)d_out;

    int E = in_sizes[1] / 2;

    detect_kernel<<<1, 32>>>((const unsigned int*)eidx);
    zero_kernel<<<(NNODES + 255) / 256, 256>>>();

    int blocks = (E + 255) / 256;
    if (blocks > 2048) blocks = 2048;
    degree_kernel<<<blocks, 256>>>(eidx, E);
    dinv_kernel<<<(NNODES + 255) / 256, 256>>>();
    gather_kernel<<<blocks, 256>>>(eidx, x, E);
    final_kernel<<<1, 32>>>(x, W1, b1, W2, b2, Wfc, bfc, out);
}